// round 12
// baseline (speedup 1.0000x reference)
#include <cuda_runtime.h>
#include <cstdint>

#define B_ 8
#define C_ 64
#define H_ 256
#define W_ 256
#define HW_ (H_ * W_)
#define TH 4                  // output rows per block
#define ROWS (TH + 2)         // staged input rows (with halo)
#define NS 6                  // ring buffers (2-channel steps need 6 for safety)
#define RSTRIDE 264           // idx3 = left zero guard, 4..259 = data, 260 = right zero guard
#define FULLMASK 0xffffffffu

__device__ __forceinline__ void cp16(uint32_t dst, const float* src) {
    asm volatile("cp.async.cg.shared.global [%0], [%1], 16;" :: "r"(dst), "l"(src));
}
__device__ __forceinline__ void cp_commit() {
    asm volatile("cp.async.commit_group;");
}
__device__ __forceinline__ void cp_wait1() {
    asm volatile("cp.async.wait_group 1;");
}

__global__ __launch_bounds__(256, 4)
void conv_attn_v12(const float* __restrict__ q, const float* __restrict__ k,
                   const float* __restrict__ v, float* __restrict__ out)
{
    __shared__ __align__(16) float ring[NS][ROWS][RSTRIDE];

    const int tid  = threadIdx.x;
    const int lane = tid & 31;
    const int x    = tid & 63;         // 64 groups of 4 px; warp = 128 contiguous px of one row
    const int y    = tid >> 6;         // output row 0..3
    const int w0   = x * 4;
    const int h0   = blockIdx.x * TH;
    const int b    = blockIdx.y;

    const size_t cb = (size_t)b * C_ * HW_;
    const float* qb = q + cb;
    const float* kb = k + cb;
    const float* vb = v + cb;
    float*       ob = out + cb;
    const int rowoff = (h0 + y) * W_ + w0;

    // zero guard cells once (never overwritten by staging)
    for (int i = tid; i < NS * ROWS; i += 256) {
        ring[i / ROWS][i % ROWS][3]   = 0.0f;
        ring[i / ROWS][i % ROWS][260] = 0.0f;
    }

    const uint32_t ring_s = (uint32_t)__cvta_generic_to_shared(&ring[0][0][0]);

    // stage channel c of tensor `srcb` into ring[wbi] (explicit buffer index, no modulo)
    auto stage = [&](const float* srcb, int c, int wbi) {
        const uint32_t bufb = ring_s + (uint32_t)wbi * (ROWS * RSTRIDE * 4);
        const float*   chan = srcb + (size_t)c * HW_;
        #pragma unroll
        for (int slot = tid; slot < ROWS * 64; slot += 256) {
            const int r   = slot >> 6;
            const int col = (slot & 63) * 4;
            const int hh  = h0 - 1 + r;
            if (hh >= 0 && hh < H_) {
                cp16(bufb + (uint32_t)(r * RSTRIDE + 4 + col) * 4, chan + hh * W_ + col);
            } else {
                float4 z = make_float4(0.f, 0.f, 0.f, 0.f);
                *reinterpret_cast<float4*>(&ring[wbi][r][4 + col]) = z;
            }
        }
    };

    float s[4][9];
#pragma unroll
    for (int j = 0; j < 4; j++)
#pragma unroll
        for (int i = 0; i < 9; i++) s[j][i] = 0.0f;

    // accumulate one channel's 3x3 taps from ring buffer `bi` into s
    auto accum = [&](int bi, const float4& qv) {
        const float qa[4] = {qv.x, qv.y, qv.z, qv.w};
#pragma unroll
        for (int dy = 0; dy < 3; dy++) {
            const float* rp = &ring[bi][y + dy][4 + w0];
            const float4 m = *reinterpret_cast<const float4*>(rp);
            float lft = __shfl_up_sync(FULLMASK, m.w, 1);
            float rgt = __shfl_down_sync(FULLMASK, m.x, 1);
            if (lane == 0)  lft = rp[-1];   // guard cell gives 0 at w=0
            if (lane == 31) rgt = rp[4];    // guard cell gives 0 at w=255

            const float a[6] = {lft, m.x, m.y, m.z, m.w, rgt};
#pragma unroll
            for (int j = 0; j < 4; j++)
#pragma unroll
                for (int dx = 0; dx < 3; dx++)
                    s[j][dy * 3 + dx] = fmaf(qa[j], a[j + dx], s[j][dy * 3 + dx]);
        }
    };

    // ================= Pass 1: scores =================
    stage(kb, 0, 0); stage(kb, 1, 1); cp_commit();
    stage(kb, 2, 2); stage(kb, 3, 3); cp_commit();
    float4 q0 = *reinterpret_cast<const float4*>(qb + rowoff);
    float4 q1 = *reinterpret_cast<const float4*>(qb + HW_ + rowoff);

    int rb = 0;    // read buffer of first channel in pair: 0,2,4,0,...
    int wb = 4;    // write buffer of first staged channel:  4,0,2,4,...
#pragma unroll 1
    for (int jp = 0; jp < C_ / 2; jp++) {
        const int c = jp * 2;
        cp_wait1();              // pair (c,c+1) complete; pair (c+2,c+3) may be pending
        __syncthreads();         // also orders last step's reads before this step's stage

        // prefetch q for next pair
        float4 q0n, q1n;
        if (c + 2 < C_) {
            q0n = *reinterpret_cast<const float4*>(qb + (size_t)(c + 2) * HW_ + rowoff);
            q1n = *reinterpret_cast<const float4*>(qb + (size_t)(c + 3) * HW_ + rowoff);
        }

        accum(rb,     q0);
        accum(rb + 1, q1);

        if (c + 4 < C_) { stage(kb, c + 4, wb); stage(kb, c + 5, wb + 1); }
        cp_commit();             // empty group on tail keeps wait accounting uniform

        q0 = q0n; q1 = q1n;
        rb += 2; if (rb == NS) rb = 0;
        wb += 2; if (wb == NS) wb = 0;
    }
    __syncthreads();             // protect ring before pass-2 prologue overwrites it

    // ================= Softmax over 9 taps (OOB taps = score 0, zero-pad semantics) =================
#pragma unroll
    for (int j = 0; j < 4; j++) {
        float mx = s[j][0];
#pragma unroll
        for (int i = 1; i < 9; i++) mx = fmaxf(mx, s[j][i]);
        float sum = 0.0f;
#pragma unroll
        for (int i = 0; i < 9; i++) { s[j][i] = __expf(s[j][i] - mx); sum += s[j][i]; }
        const float inv = 1.0f / sum;
#pragma unroll
        for (int i = 0; i < 9; i++) s[j][i] *= inv;
    }

    // weighted-v accumulation for one channel from buffer bi
    auto wsum = [&](int bi, float acc[4]) {
#pragma unroll
        for (int dy = 0; dy < 3; dy++) {
            const float* rp = &ring[bi][y + dy][4 + w0];
            const float4 m = *reinterpret_cast<const float4*>(rp);
            float lft = __shfl_up_sync(FULLMASK, m.w, 1);
            float rgt = __shfl_down_sync(FULLMASK, m.x, 1);
            if (lane == 0)  lft = rp[-1];
            if (lane == 31) rgt = rp[4];

            const float a[6] = {lft, m.x, m.y, m.z, m.w, rgt};
#pragma unroll
            for (int j = 0; j < 4; j++)
#pragma unroll
                for (int dx = 0; dx < 3; dx++)
                    acc[j] = fmaf(s[j][dy * 3 + dx], a[j + dx], acc[j]);
        }
    };

    // ================= Pass 2: weighted v sum =================
    stage(vb, 0, 0); stage(vb, 1, 1); cp_commit();
    stage(vb, 2, 2); stage(vb, 3, 3); cp_commit();

    rb = 0; wb = 4;
#pragma unroll 1
    for (int jp = 0; jp < C_ / 2; jp++) {
        const int c = jp * 2;
        cp_wait1();
        __syncthreads();

        float acc0[4] = {0.f, 0.f, 0.f, 0.f};
        float acc1[4] = {0.f, 0.f, 0.f, 0.f};
        wsum(rb,     acc0);
        wsum(rb + 1, acc1);

        if (c + 4 < C_) { stage(vb, c + 4, wb); stage(vb, c + 5, wb + 1); }
        cp_commit();

        float4 o0, o1;
        o0.x = acc0[0]; o0.y = acc0[1]; o0.z = acc0[2]; o0.w = acc0[3];
        o1.x = acc1[0]; o1.y = acc1[1]; o1.z = acc1[2]; o1.w = acc1[3];
        *reinterpret_cast<float4*>(ob + (size_t)c * HW_ + rowoff)       = o0;
        *reinterpret_cast<float4*>(ob + (size_t)(c + 1) * HW_ + rowoff) = o1;

        rb += 2; if (rb == NS) rb = 0;
        wb += 2; if (wb == NS) wb = 0;
    }
}

extern "C" void kernel_launch(void* const* d_in, const int* in_sizes, int n_in,
                              void* d_out, int out_size)
{
    const float* q = (const float*)d_in[0];
    const float* k = (const float*)d_in[1];
    const float* v = (const float*)d_in[2];
    float* out = (float*)d_out;

    dim3 block(256);
    dim3 grid(H_ / TH, B_);     // 64 x 8 = 512 blocks
    conv_attn_v12<<<grid, block>>>(q, k, v, out);
}

// round 13
// speedup vs baseline: 1.2470x; 1.2470x over previous
#include <cuda_runtime.h>
#include <cstdint>

#define B_ 8
#define C_ 64
#define H_ 256
#define W_ 256
#define HW_ (H_ * W_)
#define TH 4                  // output rows per block
#define ROWS (TH + 2)         // staged input rows (with halo)
#define NS 4                  // ring buffers
#define RSTRIDE 264           // idx3 = left zero guard, 4..259 = data, 260 = right zero guard
#define BUFBYTES (ROWS * RSTRIDE * 4)
#define FULLMASK 0xffffffffu

__device__ __forceinline__ void cp16(uint32_t dst, const float* src) {
    asm volatile("cp.async.cg.shared.global [%0], [%1], 16;" :: "r"(dst), "l"(src));
}
__device__ __forceinline__ void cp_commit() {
    asm volatile("cp.async.commit_group;");
}
__device__ __forceinline__ void cp_wait2() {
    asm volatile("cp.async.wait_group 2;");
}

__global__ __launch_bounds__(256, 4)
void conv_attn_v13(const float* __restrict__ q, const float* __restrict__ k,
                   const float* __restrict__ v, float* __restrict__ out)
{
    __shared__ __align__(16) float ring[NS][ROWS][RSTRIDE];

    const int tid  = threadIdx.x;
    const int lane = tid & 31;
    const int x    = tid & 63;          // 64 groups of 4 px; warp = 128 contiguous px of one row
    const int y    = tid >> 6;          // output row 0..3
    const int w0   = x * 4;
    const int h0   = blockIdx.x * TH;
    const int b    = blockIdx.y;

    const size_t cb = (size_t)b * C_ * HW_;
    const float* qb = q + cb;
    const float* kb = k + cb;
    const float* vb = v + cb;
    float*       ob = out + cb;
    const int rowoff = (h0 + y) * W_ + w0;

    // ---- precomputed staging slots (384 float4 slots; slot A for all, slot B for tid<128) ----
    const int  rA   = tid >> 6;               // 0..3
    const int  colA = (tid & 63) * 4;
    const int  hhA  = h0 - 1 + rA;
    const bool vA   = (hhA >= 0) && (hhA < H_);
    const int  srcA = hhA * W_ + colA;        // element offset within a channel
    const uint32_t dstA = (uint32_t)((rA * RSTRIDE + 4 + colA) * 4);

    const bool hasB = tid < 128;
    const int  rB   = 4 + (tid >> 6);         // 4..5 (valid only for tid<128)
    const int  hhB  = h0 - 1 + rB;
    const bool vB   = hasB && (hhB >= 0) && (hhB < H_);
    const int  srcB = hhB * W_ + colA;
    const uint32_t dstB = (uint32_t)((rB * RSTRIDE + 4 + colA) * 4);

    // ---- one-time init: zero guards + zero OOB rows in all buffers (never re-staged) ----
    for (int i = tid; i < NS * ROWS; i += 256) {
        ring[i / ROWS][i % ROWS][3]   = 0.0f;
        ring[i / ROWS][i % ROWS][260] = 0.0f;
    }
    {
        const float4 z = make_float4(0.f, 0.f, 0.f, 0.f);
        if (!vA)
            for (int n = 0; n < NS; n++)
                *reinterpret_cast<float4*>((char*)ring + n * BUFBYTES + dstA) = z;
        if (hasB && !vB)
            for (int n = 0; n < NS; n++)
                *reinterpret_cast<float4*>((char*)ring + n * BUFBYTES + dstB) = z;
    }

    const uint32_t ring_s = (uint32_t)__cvta_generic_to_shared(&ring[0][0][0]);

    // ---- precomputed read row bases (byte pointers; add buffer offset per channel) ----
    const char* rb0 = (const char*)ring + (uint32_t)(((y + 0) * RSTRIDE + 4 + w0) * 4);
    const char* rb1 = (const char*)ring + (uint32_t)(((y + 1) * RSTRIDE + 4 + w0) * 4);
    const char* rb2 = (const char*)ring + (uint32_t)(((y + 2) * RSTRIDE + 4 + w0) * 4);

    float s[4][9];
#pragma unroll
    for (int j = 0; j < 4; j++)
#pragma unroll
        for (int i = 0; i < 9; i++) s[j][i] = 0.0f;

    // ================= Pass 1: scores =================
    // prologue: stage channels 0..2 into buffers 0..2
#pragma unroll
    for (int c = 0; c < 3; c++) {
        if (vA) cp16(ring_s + (uint32_t)c * BUFBYTES + dstA, kb + (size_t)c * HW_ + srcA);
        if (vB) cp16(ring_s + (uint32_t)c * BUFBYTES + dstB, kb + (size_t)c * HW_ + srcB);
        cp_commit();
    }

    const float* qp  = qb + rowoff;
    float4 qcur = *reinterpret_cast<const float4*>(qp);
    const float* kpA = kb + 3 * HW_ + srcA;
    const float* kpB = kb + 3 * HW_ + srcB;

    int bo = 0;                 // read buffer byte offset
    int wo = 3 * BUFBYTES;      // write buffer byte offset
#pragma unroll 1
    for (int c = 0; c < C_; c++) {
        cp_wait2();             // channel c staged (3 pending -> 2)
        __syncthreads();        // also orders last iter's reads before this iter's stage

        const float4 qnext = *reinterpret_cast<const float4*>(qp + ((c + 1 < C_) ? HW_ : 0));
        qp += HW_;

        const float qa[4] = {qcur.x, qcur.y, qcur.z, qcur.w};
#pragma unroll
        for (int dy = 0; dy < 3; dy++) {
            const float* rp = (const float*)((dy == 0 ? rb0 : dy == 1 ? rb1 : rb2) + bo);
            const float4 m = *reinterpret_cast<const float4*>(rp);
            float lft = __shfl_up_sync(FULLMASK, m.w, 1);
            float rgt = __shfl_down_sync(FULLMASK, m.x, 1);
            if (lane == 0)  lft = rp[-1];   // guard cell: 0 at w=0
            if (lane == 31) rgt = rp[4];    // guard cell: 0 at w=255

            const float a[6] = {lft, m.x, m.y, m.z, m.w, rgt};
#pragma unroll
            for (int j = 0; j < 4; j++)
#pragma unroll
                for (int dx = 0; dx < 3; dx++)
                    s[j][dy * 3 + dx] = fmaf(qa[j], a[j + dx], s[j][dy * 3 + dx]);
        }

        if (c + 3 < C_) {
            if (vA) cp16(ring_s + (uint32_t)wo + dstA, kpA);
            if (vB) cp16(ring_s + (uint32_t)wo + dstB, kpB);
        }
        cp_commit();            // empty group on tail keeps wait accounting uniform
        kpA += HW_; kpB += HW_;
        qcur = qnext;
        bo += BUFBYTES; if (bo == NS * BUFBYTES) bo = 0;
        wo += BUFBYTES; if (wo == NS * BUFBYTES) wo = 0;
    }
    __syncthreads();            // protect ring before pass-2 prologue overwrites it

    // ================= Softmax over 9 taps (OOB taps = score 0, zero-pad semantics) =================
#pragma unroll
    for (int j = 0; j < 4; j++) {
        float mx = s[j][0];
#pragma unroll
        for (int i = 1; i < 9; i++) mx = fmaxf(mx, s[j][i]);
        float sum = 0.0f;
#pragma unroll
        for (int i = 0; i < 9; i++) { s[j][i] = __expf(s[j][i] - mx); sum += s[j][i]; }
        const float inv = 1.0f / sum;
#pragma unroll
        for (int i = 0; i < 9; i++) s[j][i] *= inv;
    }

    // ================= Pass 2: weighted v sum =================
#pragma unroll
    for (int c = 0; c < 3; c++) {
        if (vA) cp16(ring_s + (uint32_t)c * BUFBYTES + dstA, vb + (size_t)c * HW_ + srcA);
        if (vB) cp16(ring_s + (uint32_t)c * BUFBYTES + dstB, vb + (size_t)c * HW_ + srcB);
        cp_commit();
    }

    const float* vpA = vb + 3 * HW_ + srcA;
    const float* vpB = vb + 3 * HW_ + srcB;
    float* op = ob + rowoff;

    bo = 0; wo = 3 * BUFBYTES;
#pragma unroll 1
    for (int c = 0; c < C_; c++) {
        cp_wait2();
        __syncthreads();

        float acc[4] = {0.f, 0.f, 0.f, 0.f};
#pragma unroll
        for (int dy = 0; dy < 3; dy++) {
            const float* rp = (const float*)((dy == 0 ? rb0 : dy == 1 ? rb1 : rb2) + bo);
            const float4 m = *reinterpret_cast<const float4*>(rp);
            float lft = __shfl_up_sync(FULLMASK, m.w, 1);
            float rgt = __shfl_down_sync(FULLMASK, m.x, 1);
            if (lane == 0)  lft = rp[-1];
            if (lane == 31) rgt = rp[4];

            const float a[6] = {lft, m.x, m.y, m.z, m.w, rgt};
#pragma unroll
            for (int j = 0; j < 4; j++)
#pragma unroll
                for (int dx = 0; dx < 3; dx++)
                    acc[j] = fmaf(s[j][dy * 3 + dx], a[j + dx], acc[j]);
        }

        if (c + 3 < C_) {
            if (vA) cp16(ring_s + (uint32_t)wo + dstA, vpA);
            if (vB) cp16(ring_s + (uint32_t)wo + dstB, vpB);
        }
        cp_commit();
        vpA += HW_; vpB += HW_;

        float4 o;
        o.x = acc[0]; o.y = acc[1]; o.z = acc[2]; o.w = acc[3];
        *reinterpret_cast<float4*>(op) = o;
        op += HW_;

        bo += BUFBYTES; if (bo == NS * BUFBYTES) bo = 0;
        wo += BUFBYTES; if (wo == NS * BUFBYTES) wo = 0;
    }
}

extern "C" void kernel_launch(void* const* d_in, const int* in_sizes, int n_in,
                              void* d_out, int out_size)
{
    const float* q = (const float*)d_in[0];
    const float* k = (const float*)d_in[1];
    const float* v = (const float*)d_in[2];
    float* out = (float*)d_out;

    dim3 block(256);
    dim3 grid(H_ / TH, B_);     // 64 x 8 = 512 blocks
    conv_attn_v13<<<grid, block>>>(q, k, v, out);
}

// round 14
// speedup vs baseline: 1.2657x; 1.0150x over previous
#include <cuda_runtime.h>
#include <cstdint>

#define B_ 8
#define C_ 64
#define H_ 256
#define W_ 256
#define HW_ (H_ * W_)
#define TH 4                  // output rows per block
#define ROWS 6                // staged rows (with halo)
#define NS 4                  // ring buffers
#define ROWB (W_ * 4)         // 1024 bytes per smem row (dense)
#define BUFB (ROWS * ROWB)    // 6144 bytes per buffer
#define FULLMASK 0xffffffffu

__device__ __forceinline__ uint32_t smem_u32(const void* p) {
    return (uint32_t)__cvta_generic_to_shared(p);
}
__device__ __forceinline__ void mbar_init(uint32_t mb, uint32_t cnt) {
    asm volatile("mbarrier.init.shared.b64 [%0], %1;" :: "r"(mb), "r"(cnt) : "memory");
}
__device__ __forceinline__ void mbar_expect_tx(uint32_t mb, uint32_t bytes) {
    asm volatile("mbarrier.arrive.expect_tx.shared.b64 _, [%0], %1;"
                 :: "r"(mb), "r"(bytes) : "memory");
}
__device__ __forceinline__ void bulk_g2s(uint32_t dst, const void* src, uint32_t bytes, uint32_t mb) {
    asm volatile("cp.async.bulk.shared::cta.global.mbarrier::complete_tx::bytes [%0], [%1], %2, [%3];"
                 :: "r"(dst), "l"(src), "r"(bytes), "r"(mb) : "memory");
}
__device__ __forceinline__ void mbar_wait(uint32_t mb, uint32_t parity) {
    uint32_t done;
    asm volatile("{\n\t.reg .pred p;\n\t"
                 "mbarrier.try_wait.parity.acquire.cta.shared::cta.b64 p, [%1], %2;\n\t"
                 "selp.b32 %0, 1, 0, p;\n\t}"
                 : "=r"(done) : "r"(mb), "r"(parity) : "memory");
    if (!done) {
        asm volatile("{\n\t.reg .pred P1;\n\t"
                     "WL%=:\n\t"
                     "mbarrier.try_wait.parity.acquire.cta.shared::cta.b64 P1, [%0], %1, 0x989680;\n\t"
                     "@P1 bra.uni WD%=;\n\t"
                     "bra.uni WL%=;\n\t"
                     "WD%=:\n\t}"
                     :: "r"(mb), "r"(parity) : "memory");
    }
}

__global__ __launch_bounds__(256, 4)
void conv_attn_v14(const float* __restrict__ q, const float* __restrict__ k,
                   const float* __restrict__ v, float* __restrict__ out)
{
    __shared__ __align__(16) float ring[NS][ROWS][W_];
    __shared__ uint64_t mbar[NS];

    const int tid  = threadIdx.x;
    const int lane = tid & 31;
    const int x    = tid & 63;          // 64 groups of 4 px; warp = 128 contiguous px of one row
    const int y    = tid >> 6;          // output row 0..3
    const int w0   = x * 4;
    const int h0   = blockIdx.x * TH;
    const int b    = blockIdx.y;

    const size_t cb = (size_t)b * C_ * HW_;
    const float* qb = q + cb;
    const float* kb = k + cb;
    const float* vb = v + cb;
    float*       ob = out + cb;
    const int rowoff = (h0 + y) * W_ + w0;

    // row validity (block-uniform): staged rows r=0..5 map to hh = h0-1+r
    const bool rv0 = (h0 > 0);          // r=0 valid
    const bool rv5 = (h0 + 4 < H_);     // r=5 valid
    const uint32_t txbytes = (uint32_t)((4 + (rv0 ? 1 : 0) + (rv5 ? 1 : 0))) * ROWB;

    // zero never-staged border rows once (one float per thread per buffer)
    if (!rv0) for (int n = 0; n < NS; n++) ring[n][0][tid] = 0.0f;
    if (!rv5) for (int n = 0; n < NS; n++) ring[n][5][tid] = 0.0f;

    const uint32_t ring_s = smem_u32(&ring[0][0][0]);
    const uint32_t mb0 = smem_u32(&mbar[0]);
    if (tid < NS) mbar_init(mb0 + tid * 8, 1);
    __syncthreads();

    // producer (tid 0 only): stage channel c of srcb into buffer bi
    auto stage = [&](const float* srcb, int c, int bi) {
        const uint32_t mb = mb0 + bi * 8;
        mbar_expect_tx(mb, txbytes);
        const float* chan = srcb + (size_t)c * HW_ + (size_t)h0 * W_;  // row h0 base
        const uint32_t dstb = ring_s + (uint32_t)bi * BUFB;
        #pragma unroll
        for (int r = 0; r < ROWS; r++) {
            if (r == 0 && !rv0) continue;
            if (r == 5 && !rv5) continue;
            bulk_g2s(dstb + (uint32_t)r * ROWB, chan + (r - 1) * W_, ROWB, mb);
        }
    };

    // edge-tap predicates (per-thread constants)
    const bool el = (w0 > 0);           // lane 0 left tap exists
    const bool er = (w0 + 4 < W_);      // lane 31 right tap exists

    // read row base pointers (add buffer byte offset per channel)
    const char* rb0 = (const char*)ring + (uint32_t)(y * ROWB + w0 * 4);
    const char* rb1 = rb0 + ROWB;
    const char* rb2 = rb1 + ROWB;

    float s[4][9];
#pragma unroll
    for (int j = 0; j < 4; j++)
#pragma unroll
        for (int i = 0; i < 9; i++) s[j][i] = 0.0f;

    uint32_t phases = 0;

    // ================= Pass 1: scores =================
    if (tid == 0) { stage(kb, 0, 0); stage(kb, 1, 1); stage(kb, 2, 2); }

    const float* qp = qb + rowoff;
    float4 qcur = *reinterpret_cast<const float4*>(qp);

    int bo = 0;
#pragma unroll 1
    for (int c = 0; c < C_; c++) {
        const int bi = c & 3;
        mbar_wait(mb0 + bi * 8, (phases >> bi) & 1);
        phases ^= 1u << bi;
        __syncthreads();        // WAR edge: last iter's reads precede this iter's stage

        const float4 qnext = *reinterpret_cast<const float4*>(qp + ((c + 1 < C_) ? HW_ : 0));
        qp += HW_;

        const float qa[4] = {qcur.x, qcur.y, qcur.z, qcur.w};
#pragma unroll
        for (int dy = 0; dy < 3; dy++) {
            const float* rp = (const float*)((dy == 0 ? rb0 : dy == 1 ? rb1 : rb2) + bo);
            const float4 m = *reinterpret_cast<const float4*>(rp);
            float lft = __shfl_up_sync(FULLMASK, m.w, 1);
            float rgt = __shfl_down_sync(FULLMASK, m.x, 1);
            if (lane == 0)  lft = el ? rp[-1] : 0.0f;
            if (lane == 31) rgt = er ? rp[4]  : 0.0f;

            const float a[6] = {lft, m.x, m.y, m.z, m.w, rgt};
#pragma unroll
            for (int j = 0; j < 4; j++)
#pragma unroll
                for (int dx = 0; dx < 3; dx++)
                    s[j][dy * 3 + dx] = fmaf(qa[j], a[j + dx], s[j][dy * 3 + dx]);
        }

        if (tid == 0 && c + 3 < C_) stage(kb, c + 3, (c + 3) & 3);
        qcur = qnext;
        bo += BUFB; if (bo == NS * BUFB) bo = 0;
    }
    __syncthreads();            // protect ring before pass-2 staging overwrites it

    // ================= Softmax over 9 taps (OOB taps = score 0, zero-pad semantics) =================
#pragma unroll
    for (int j = 0; j < 4; j++) {
        float mx = s[j][0];
#pragma unroll
        for (int i = 1; i < 9; i++) mx = fmaxf(mx, s[j][i]);
        float sum = 0.0f;
#pragma unroll
        for (int i = 0; i < 9; i++) { s[j][i] = __expf(s[j][i] - mx); sum += s[j][i]; }
        const float inv = 1.0f / sum;
#pragma unroll
        for (int i = 0; i < 9; i++) s[j][i] *= inv;
    }

    // ================= Pass 2: weighted v sum =================
    if (tid == 0) { stage(vb, 0, 0); stage(vb, 1, 1); stage(vb, 2, 2); }

    const float* opq = vb;  (void)opq;
    float* op = ob + rowoff;

    bo = 0;
#pragma unroll 1
    for (int c = 0; c < C_; c++) {
        const int bi = c & 3;
        mbar_wait(mb0 + bi * 8, (phases >> bi) & 1);
        phases ^= 1u << bi;
        __syncthreads();

        float acc[4] = {0.f, 0.f, 0.f, 0.f};
#pragma unroll
        for (int dy = 0; dy < 3; dy++) {
            const float* rp = (const float*)((dy == 0 ? rb0 : dy == 1 ? rb1 : rb2) + bo);
            const float4 m = *reinterpret_cast<const float4*>(rp);
            float lft = __shfl_up_sync(FULLMASK, m.w, 1);
            float rgt = __shfl_down_sync(FULLMASK, m.x, 1);
            if (lane == 0)  lft = el ? rp[-1] : 0.0f;
            if (lane == 31) rgt = er ? rp[4]  : 0.0f;

            const float a[6] = {lft, m.x, m.y, m.z, m.w, rgt};
#pragma unroll
            for (int j = 0; j < 4; j++)
#pragma unroll
                for (int dx = 0; dx < 3; dx++)
                    acc[j] = fmaf(s[j][dy * 3 + dx], a[j + dx], acc[j]);
        }

        if (tid == 0 && c + 3 < C_) stage(vb, c + 3, (c + 3) & 3);

        float4 o;
        o.x = acc[0]; o.y = acc[1]; o.z = acc[2]; o.w = acc[3];
        *reinterpret_cast<float4*>(op) = o;
        op += HW_;
        bo += BUFB; if (bo == NS * BUFB) bo = 0;
    }
}

extern "C" void kernel_launch(void* const* d_in, const int* in_sizes, int n_in,
                              void* d_out, int out_size)
{
    const float* q = (const float*)d_in[0];
    const float* k = (const float*)d_in[1];
    const float* v = (const float*)d_in[2];
    float* out = (float*)d_out;

    dim3 block(256);
    dim3 grid(H_ / TH, B_);     // 64 x 8 = 512 blocks
    conv_attn_v14<<<grid, block>>>(q, k, v, out);
}